// round 5
// baseline (speedup 1.0000x reference)
#include <cuda_runtime.h>
#include <cstdint>

// Problem constants
#define Bz   32
#define Nseq 512
#define Dm   1024
#define Hh   16
#define DHd  64
#define Mtot (Bz * Nseq)          // 16384
#define NT3  (3 * Dm)             // 3072

// ---------------------------------------------------------------------------
// Scratch (allocation-free rule: __device__ globals)
// ---------------------------------------------------------------------------
__device__ float g_kqv_v[Mtot * NT3];     // [m, 3072]: k | q | v per token (v modality)
__device__ float g_kqv_t[Mtot * NT3];     // t modality
__device__ float g_upd_v[Mtot * Dm];      // attention update (v)
__device__ float g_upd_t[Mtot * Dm];      // attention update (t)
__device__ float g_mean[2][Bz * Dm];      // [0]=v_mean, [1]=t_mean
__device__ float g_gate[2][Bz * Dm];      // [0]=gate used by v attn (t4v), [1]=gate used by t attn (v4t)

// ---------------------------------------------------------------------------
// Fast exp on the FMA pipe (avoids MUFU bottleneck). Valid for x <= ~0.
// ---------------------------------------------------------------------------
__device__ __forceinline__ float fexp(float x) {
    x = fmaxf(x, -80.0f);
    float z  = fmaf(x, 1.4426950408889634f, 12582912.0f);  // round to nearest int (magic)
    int   ni = __float_as_int(z) - 0x4B400000;
    float nf = (float)ni;
    float r  = fmaf(nf, -0.693359375f, x);                 // x - n*ln2_hi
    r        = fmaf(nf, 2.12194440e-4f, r);                // - n*ln2_lo
    float p  = 1.9875691500e-4f;
    p = fmaf(p, r, 1.3981999507e-3f);
    p = fmaf(p, r, 8.3334519073e-3f);
    p = fmaf(p, r, 4.1665795894e-2f);
    p = fmaf(p, r, 1.6666665459e-1f);
    p = fmaf(p, r, 5.0000001201e-1f);
    float e = fmaf(r * r, p, r) + 1.0f;                    // exp(r) in [~0.7, ~1.42]
    return __int_as_float(__float_as_int(e) + (ni << 23)); // * 2^n
}

// ---------------------------------------------------------------------------
// Kernel 1: masked mean over sequence -> g_mean[z][b*Dm + d]
// grid (Dm/256, Bz, 2), block 256
// ---------------------------------------------------------------------------
__global__ __launch_bounds__(256) void mean_kernel(
    const float* __restrict__ v, const float* __restrict__ t,
    const float* __restrict__ vm, const float* __restrict__ tm)
{
    const int z = blockIdx.z;
    const int b = blockIdx.y;
    const float* X  = z ? t  : v;
    const float* mk = z ? tm : vm;

    __shared__ float s_mk[Nseq];
    __shared__ float s_red[256];

    const int tid = threadIdx.x;
    float c = 0.f;
    for (int n = tid; n < Nseq; n += 256) {
        float m = mk[b * Nseq + n];
        s_mk[n] = m;
        c += m;
    }
    s_red[tid] = c;
    __syncthreads();
    for (int s = 128; s > 0; s >>= 1) {
        if (tid < s) s_red[tid] += s_red[tid + s];
        __syncthreads();
    }
    const float inv = 1.0f / s_red[0];

    const int d = blockIdx.x * 256 + tid;
    float acc = 0.f;
    for (int n = 0; n < Nseq; n++)
        acc = fmaf(X[(size_t)(b * Nseq + n) * Dm + d], s_mk[n], acc);
    g_mean[z][b * Dm + d] = acc * inv;
}

// ---------------------------------------------------------------------------
// Kernel 2: gates. z=0: gate-for-v = sigmoid(relu(t_mean) @ W_t4v + b_t4v)
//                  z=1: gate-for-t = sigmoid(relu(v_mean) @ W_v4t + b_v4t)
// grid (Dm/128, Bz, 2), block 128
// ---------------------------------------------------------------------------
__global__ __launch_bounds__(128) void gate_kernel(
    const float* __restrict__ W_v4t, const float* __restrict__ b_v4t,
    const float* __restrict__ W_t4v, const float* __restrict__ b_t4v)
{
    const int z = blockIdx.z;
    const int b = blockIdx.y;
    const float* mean = g_mean[z ^ 1];          // z=0 uses t_mean(idx1), z=1 uses v_mean(idx0)
    const float* W    = z ? W_v4t : W_t4v;
    const float* bias = z ? b_v4t : b_t4v;

    __shared__ float s_m[Dm];
    const int tid = threadIdx.x;
    for (int i = tid; i < Dm; i += 128)
        s_m[i] = fmaxf(mean[b * Dm + i], 0.f);
    __syncthreads();

    const int j = blockIdx.x * 128 + tid;
    float acc = bias[j];
    for (int i = 0; i < Dm; i++)
        acc = fmaf(s_m[i], W[(size_t)i * Dm + j], acc);
    g_gate[z][b * Dm + j] = 1.0f / (1.0f + fexp(-fabsf(acc))) ;
    // sigmoid(x) = 1/(1+e^-x); handle both signs correctly:
    float s = 1.0f / (1.0f + fexp(-fabsf(acc)));
    g_gate[z][b * Dm + j] = (acc >= 0.f) ? s : (1.0f - s);
}

// ---------------------------------------------------------------------------
// Kernel 3: KQV GEMM.  out[m, c] = (relu(X[m,:]) @ W)[c] + bias[c], then
//   * mask[m]; K & Q columns also * (1 + gate[b, c%1024]); Q also * 0.125.
// 128x128x8 tiling, 256 threads, 8x8 per-thread tile, reg-prefetch double buffer.
// grid (3072/128=24, 16384/128=128, 2), block 256
// ---------------------------------------------------------------------------
__global__ __launch_bounds__(256) void kqv_kernel(
    const float* __restrict__ v,  const float* __restrict__ t,
    const float* __restrict__ Wv, const float* __restrict__ bv,
    const float* __restrict__ Wt, const float* __restrict__ bt,
    const float* __restrict__ vm, const float* __restrict__ tm)
{
    const int z = blockIdx.z;
    const float* X    = z ? t  : v;
    const float* W    = z ? Wt : Wv;
    const float* bias = z ? bt : bv;
    const float* mk   = z ? tm : vm;
    float* out        = z ? g_kqv_t : g_kqv_v;
    const float* gate = g_gate[z];

    const int n0 = blockIdx.x * 128;
    const int m0 = blockIdx.y * 128;
    const int tid = threadIdx.x;
    const int tx = tid & 15;          // 0..15 -> cols
    const int ty = tid >> 4;          // 0..15 -> rows

    __shared__ float As[8][128];
    __shared__ float Bs[8][128];

    float acc[8][8];
#pragma unroll
    for (int i = 0; i < 8; i++)
#pragma unroll
        for (int j = 0; j < 8; j++) acc[i][j] = 0.f;

    const int arow = tid >> 1;          // 0..127
    const int acol = (tid & 1) * 4;     // 0 / 4
    const int brow = tid >> 5;          // 0..7
    const int bcol = (tid & 31) * 4;    // 0..124

    const float* Aptr = X + (size_t)(m0 + arow) * Dm + acol;
    const float* Bptr = W + (size_t)brow * NT3 + n0 + bcol;

    float4 a_nxt = *reinterpret_cast<const float4*>(Aptr);
    float4 b_nxt = *reinterpret_cast<const float4*>(Bptr);

    for (int kb = 0; kb < Dm / 8; kb++) {
        As[acol + 0][arow] = fmaxf(a_nxt.x, 0.f);
        As[acol + 1][arow] = fmaxf(a_nxt.y, 0.f);
        As[acol + 2][arow] = fmaxf(a_nxt.z, 0.f);
        As[acol + 3][arow] = fmaxf(a_nxt.w, 0.f);
        *reinterpret_cast<float4*>(&Bs[brow][bcol]) = b_nxt;
        __syncthreads();

        if (kb + 1 < Dm / 8) {
            a_nxt = *reinterpret_cast<const float4*>(Aptr + (kb + 1) * 8);
            b_nxt = *reinterpret_cast<const float4*>(Bptr + (size_t)(kb + 1) * 8 * NT3);
        }

#pragma unroll
        for (int kk = 0; kk < 8; kk++) {
            float4 a0 = *reinterpret_cast<const float4*>(&As[kk][ty * 8]);
            float4 a1 = *reinterpret_cast<const float4*>(&As[kk][ty * 8 + 4]);
            float4 c0 = *reinterpret_cast<const float4*>(&Bs[kk][tx * 8]);
            float4 c1 = *reinterpret_cast<const float4*>(&Bs[kk][tx * 8 + 4]);
            float a[8] = {a0.x, a0.y, a0.z, a0.w, a1.x, a1.y, a1.z, a1.w};
            float bb[8] = {c0.x, c0.y, c0.z, c0.w, c1.x, c1.y, c1.z, c1.w};
#pragma unroll
            for (int i = 0; i < 8; i++)
#pragma unroll
                for (int j = 0; j < 8; j++)
                    acc[i][j] = fmaf(a[i], bb[j], acc[i][j]);
        }
        __syncthreads();
    }

    // epilogue
    const int batch = m0 >> 9;  // uniform per block (128 | 512)
    float bs[8], gf[8];
#pragma unroll
    for (int j = 0; j < 8; j++) {
        const int c = n0 + tx * 8 + j;
        bs[j] = bias[c];
        float f = 1.0f;
        if (c < 2 * Dm) {
            f = 1.0f + gate[batch * Dm + (c & (Dm - 1))];
            if (c >= Dm) f *= 0.125f;   // fold 1/sqrt(dh) into Q
        }
        gf[j] = f;
    }
#pragma unroll
    for (int i = 0; i < 8; i++) {
        const int m = m0 + ty * 8 + i;
        const float msk = mk[batch * Nseq + (m & (Nseq - 1))];
        float r[8];
#pragma unroll
        for (int j = 0; j < 8; j++)
            r[j] = (acc[i][j] + bs[j]) * msk * gf[j];
        float* dst = out + (size_t)m * NT3 + n0 + tx * 8;
        *reinterpret_cast<float4*>(dst)     = make_float4(r[0], r[1], r[2], r[3]);
        *reinterpret_cast<float4*>(dst + 4) = make_float4(r[4], r[5], r[6], r[7]);
    }
}

// ---------------------------------------------------------------------------
// Kernel 4: fused attention (online softmax), per (b, h, 32-q-row tile).
// Q/K already carry gate & 1/sqrt(dh). 8-thread groups own one q row;
// lane-in-group owns 8 k-cols (scores) / 8 output dims (PV).
// grid (Nseq/32=16, Hh=16, Bz*2=64), block 256
// ---------------------------------------------------------------------------
__global__ __launch_bounds__(256) void attn_kernel(
    const float* __restrict__ vm, const float* __restrict__ tm)
{
    const int b = blockIdx.z & (Bz - 1);
    const int z = blockIdx.z >> 5;
    const int h = blockIdx.y;
    const int q0 = blockIdx.x * 32;
    const float* kqv = z ? g_kqv_t : g_kqv_v;
    const float* mk  = z ? tm : vm;
    float* upd       = z ? g_upd_t : g_upd_v;

    __shared__ float s_q[32][68];
    __shared__ float s_kt[64][68];   // transposed: [kd][kcol]; reused as p[32][68]
    __shared__ float s_v[64][68];    // [kcol][kd]
    __shared__ float s_m[Nseq];

    const int tid = threadIdx.x;

    {   // Q tile: 32 rows x 64
        const int r = tid >> 3, c = (tid & 7) * 8;
        const float* src = kqv + (size_t)(b * Nseq + q0 + r) * NT3 + Dm + h * DHd + c;
        float4 x0 = *reinterpret_cast<const float4*>(src);
        float4 x1 = *reinterpret_cast<const float4*>(src + 4);
        s_q[r][c + 0] = x0.x; s_q[r][c + 1] = x0.y; s_q[r][c + 2] = x0.z; s_q[r][c + 3] = x0.w;
        s_q[r][c + 4] = x1.x; s_q[r][c + 5] = x1.y; s_q[r][c + 6] = x1.z; s_q[r][c + 7] = x1.w;
    }
    for (int n = tid; n < Nseq; n += 256) s_m[n] = mk[b * Nseq + n];
    __syncthreads();

    const int qr = tid >> 3;
    const int g8 = tid & 7;
    float m_run = -1e30f, l_run = 0.f;
    float o[8] = {0.f, 0.f, 0.f, 0.f, 0.f, 0.f, 0.f, 0.f};

    for (int kt = 0; kt < Nseq; kt += 64) {
        {   // load K (transposed) and V tiles: 64 x 64 each
            const int r = tid >> 2, c = (tid & 3) * 16;
            const float* kbp = kqv + (size_t)(b * Nseq + kt + r) * NT3 + h * DHd + c;
            const float* vbp = kbp + 2 * Dm;
#pragma unroll
            for (int i = 0; i < 4; i++) {
                float4 k4 = *reinterpret_cast<const float4*>(kbp + i * 4);
                s_kt[c + i * 4 + 0][r] = k4.x;
                s_kt[c + i * 4 + 1][r] = k4.y;
                s_kt[c + i * 4 + 2][r] = k4.z;
                s_kt[c + i * 4 + 3][r] = k4.w;
                *reinterpret_cast<float4*>(&s_v[r][c + i * 4]) =
                    *reinterpret_cast<const float4*>(vbp + i * 4);
            }
        }
        __syncthreads();

        float sc[8] = {0.f, 0.f, 0.f, 0.f, 0.f, 0.f, 0.f, 0.f};
#pragma unroll 8
        for (int kd = 0; kd < DHd; kd++) {
            const float qv = s_q[qr][kd];
            float4 k0 = *reinterpret_cast<const float4*>(&s_kt[kd][g8 * 8]);
            float4 k1 = *reinterpret_cast<const float4*>(&s_kt[kd][g8 * 8 + 4]);
            sc[0] = fmaf(qv, k0.x, sc[0]); sc[1] = fmaf(qv, k0.y, sc[1]);
            sc[2] = fmaf(qv, k0.z, sc[2]); sc[3] = fmaf(qv, k0.w, sc[3]);
            sc[4] = fmaf(qv, k1.x, sc[4]); sc[5] = fmaf(qv, k1.y, sc[5]);
            sc[6] = fmaf(qv, k1.z, sc[6]); sc[7] = fmaf(qv, k1.w, sc[7]);
        }
#pragma unroll
        for (int kk = 0; kk < 8; kk++)
            if (s_m[kt + g8 * 8 + kk] == 0.f) sc[kk] = -1e30f;

        float tmax = sc[0];
#pragma unroll
        for (int kk = 1; kk < 8; kk++) tmax = fmaxf(tmax, sc[kk]);
#pragma unroll
        for (int off = 4; off; off >>= 1)
            tmax = fmaxf(tmax, __shfl_xor_sync(0xffffffffu, tmax, off));

        const float nm = fmaxf(m_run, tmax);
        const float corr = fexp(m_run - nm);

        __syncthreads();                       // all score reads of s_kt done
        float (*s_p)[68] = s_kt;               // reuse K tile storage for p

        float ps = 0.f;
#pragma unroll
        for (int kk = 0; kk < 8; kk++) {
            float p = (sc[kk] < -1e29f) ? 0.f : fexp(sc[kk] - nm);
            s_p[qr][g8 * 8 + kk] = p;
            ps += p;
        }
#pragma unroll
        for (int off = 4; off; off >>= 1)
            ps += __shfl_xor_sync(0xffffffffu, ps, off);

        l_run = l_run * corr + ps;
        m_run = nm;
#pragma unroll
        for (int j = 0; j < 8; j++) o[j] *= corr;
        __syncwarp();

#pragma unroll 4
        for (int k = 0; k < 64; k++) {
            const float p = s_p[qr][k];
            float4 v0 = *reinterpret_cast<const float4*>(&s_v[k][g8 * 8]);
            float4 v1 = *reinterpret_cast<const float4*>(&s_v[k][g8 * 8 + 4]);
            o[0] = fmaf(p, v0.x, o[0]); o[1] = fmaf(p, v0.y, o[1]);
            o[2] = fmaf(p, v0.z, o[2]); o[3] = fmaf(p, v0.w, o[3]);
            o[4] = fmaf(p, v1.x, o[4]); o[5] = fmaf(p, v1.y, o[5]);
            o[6] = fmaf(p, v1.z, o[6]); o[7] = fmaf(p, v1.w, o[7]);
        }
        __syncthreads();
    }

    const float inv = 1.0f / l_run;
    float* dst = upd + (size_t)(b * Nseq + q0 + qr) * Dm + h * DHd + g8 * 8;
    *reinterpret_cast<float4*>(dst) =
        make_float4(o[0] * inv, o[1] * inv, o[2] * inv, o[3] * inv);
    *reinterpret_cast<float4*>(dst + 4) =
        make_float4(o[4] * inv, o[5] * inv, o[6] * inv, o[7] * inv);
}

// ---------------------------------------------------------------------------
// Kernel 5: output projection. out = (X + upd) @ W_o + b_o
// Same 128x128x8 tiling. grid (1024/128=8, 128, 2), block 256
// ---------------------------------------------------------------------------
__global__ __launch_bounds__(256) void proj_kernel(
    const float* __restrict__ v,   const float* __restrict__ t,
    const float* __restrict__ Wvo, const float* __restrict__ bvo,
    const float* __restrict__ Wto, const float* __restrict__ bto,
    float* __restrict__ out)
{
    const int z = blockIdx.z;
    const float* X    = z ? t   : v;
    const float* U    = z ? g_upd_t : g_upd_v;
    const float* W    = z ? Wto : Wvo;
    const float* bias = z ? bto : bvo;
    float* O          = out + (size_t)z * Mtot * Dm;

    const int n0 = blockIdx.x * 128;
    const int m0 = blockIdx.y * 128;
    const int tid = threadIdx.x;
    const int tx = tid & 15;
    const int ty = tid >> 4;

    __shared__ float As[8][128];
    __shared__ float Bs[8][128];

    float acc[8][8];
#pragma unroll
    for (int i = 0; i < 8; i++)
#pragma unroll
        for (int j = 0; j < 8; j++) acc[i][j] = 0.f;

    const int arow = tid >> 1;
    const int acol = (tid & 1) * 4;
    const int brow = tid >> 5;
    const int bcol = (tid & 31) * 4;

    const float* Aptr = X + (size_t)(m0 + arow) * Dm + acol;
    const float* Uptr = U + (size_t)(m0 + arow) * Dm + acol;
    const float* Bptr = W + (size_t)brow * Dm + n0 + bcol;

    float4 a_nxt = *reinterpret_cast<const float4*>(Aptr);
    float4 u_nxt = *reinterpret_cast<const float4*>(Uptr);
    float4 b_nxt = *reinterpret_cast<const float4*>(Bptr);

    for (int kb = 0; kb < Dm / 8; kb++) {
        As[acol + 0][arow] = a_nxt.x + u_nxt.x;
        As[acol + 1][arow] = a_nxt.y + u_nxt.y;
        As[acol + 2][arow] = a_nxt.z + u_nxt.z;
        As[acol + 3][arow] = a_nxt.w + u_nxt.w;
        *reinterpret_cast<float4*>(&Bs[brow][bcol]) = b_nxt;
        __syncthreads();

        if (kb + 1 < Dm / 8) {
            a_nxt = *reinterpret_cast<const float4*>(Aptr + (kb + 1) * 8);
            u_nxt = *reinterpret_cast<const float4*>(Uptr + (kb + 1) * 8);
            b_nxt = *reinterpret_cast<const float4*>(Bptr + (size_t)(kb + 1) * 8 * Dm);
        }

#pragma unroll
        for (int kk = 0; kk < 8; kk++) {
            float4 a0 = *reinterpret_cast<const float4*>(&As[kk][ty * 8]);
            float4 a1 = *reinterpret_cast<const float4*>(&As[kk][ty * 8 + 4]);
            float4 c0 = *reinterpret_cast<const float4*>(&Bs[kk][tx * 8]);
            float4 c1 = *reinterpret_cast<const float4*>(&Bs[kk][tx * 8 + 4]);
            float a[8] = {a0.x, a0.y, a0.z, a0.w, a1.x, a1.y, a1.z, a1.w};
            float bb[8] = {c0.x, c0.y, c0.z, c0.w, c1.x, c1.y, c1.z, c1.w};
#pragma unroll
            for (int i = 0; i < 8; i++)
#pragma unroll
                for (int j = 0; j < 8; j++)
                    acc[i][j] = fmaf(a[i], bb[j], acc[i][j]);
        }
        __syncthreads();
    }

    float bs[8];
#pragma unroll
    for (int j = 0; j < 8; j++) bs[j] = bias[n0 + tx * 8 + j];
#pragma unroll
    for (int i = 0; i < 8; i++) {
        const int m = m0 + ty * 8 + i;
        float r[8];
#pragma unroll
        for (int j = 0; j < 8; j++) r[j] = acc[i][j] + bs[j];
        float* dst = O + (size_t)m * Dm + n0 + tx * 8;
        *reinterpret_cast<float4*>(dst)     = make_float4(r[0], r[1], r[2], r[3]);
        *reinterpret_cast<float4*>(dst + 4) = make_float4(r[4], r[5], r[6], r[7]);
    }
}

// ---------------------------------------------------------------------------
// Launch
// ---------------------------------------------------------------------------
extern "C" void kernel_launch(void* const* d_in, const int* in_sizes, int n_in,
                              void* d_out, int out_size)
{
    const float* v     = (const float*)d_in[0];
    const float* t     = (const float*)d_in[1];
    const float* vm    = (const float*)d_in[2];
    const float* tm    = (const float*)d_in[3];
    const float* W_v4t = (const float*)d_in[4];
    const float* b_v4t = (const float*)d_in[5];
    const float* W_t4v = (const float*)d_in[6];
    const float* b_t4v = (const float*)d_in[7];
    const float* W_v   = (const float*)d_in[8];
    const float* b_v   = (const float*)d_in[9];
    const float* W_t   = (const float*)d_in[10];
    const float* b_t   = (const float*)d_in[11];
    const float* W_vo  = (const float*)d_in[12];
    const float* b_vo  = (const float*)d_in[13];
    const float* W_to  = (const float*)d_in[14];
    const float* b_to  = (const float*)d_in[15];
    float* out = (float*)d_out;

    mean_kernel<<<dim3(Dm / 256, Bz, 2), 256>>>(v, t, vm, tm);
    gate_kernel<<<dim3(Dm / 128, Bz, 2), 128>>>(W_v4t, b_v4t, W_t4v, b_t4v);
    kqv_kernel<<<dim3(NT3 / 128, Mtot / 128, 2), 256>>>(v, t, W_v, b_v, W_t, b_t, vm, tm);
    attn_kernel<<<dim3(Nseq / 32, Hh, Bz * 2), 256>>>(vm, tm);
    proj_kernel<<<dim3(Dm / 128, Mtot / 128, 2), 256>>>(v, t, W_vo, b_vo, W_to, b_to, out);
}